// round 8
// baseline (speedup 1.0000x reference)
#include <cuda_runtime.h>
#include <cuda_bf16.h>

#define NIDS    33                    // ids 0..32 (0 = background)
#define NBINS   1089                  // 33*33
#define THREADS 1024                  // 32 warps, 1 CTA/SM (smem-limited)
#define NREP    16                    // replicated global histograms
#define CNT_WORDS (NBINS * 32)        // cnt[bin][lane] u32
#define SMEM_DYN  (CNT_WORDS * 4)     // 139,392 B

// Scratch (zero at load; finalize block resets after every call)
__device__ int          g_rep[NREP][NBINS];
__device__ unsigned int g_ticket;

__global__ void __launch_bounds__(THREADS, 1)
fused_iou_kernel(const float4* __restrict__ p4, const float4* __restrict__ t4,
                 int n4,
                 const float* __restrict__ pf, const float* __restrict__ tf,
                 int n, float* __restrict__ out, int nblocks)
{
    extern __shared__ int cnt[];      // [bin*32 + lane]: bank = lane -> conflict-free atomics
    __shared__ float psum[NIDS], tsum[NIDS], part[NIDS];
    __shared__ int   s_last;

    int tid  = threadIdx.x;
    int lane = tid & 31;
    int w    = tid >> 5;

    // ---- zero counters (139 KB, 8.5 uint4 stores/thread) ----
    {
        uint4* z4 = (uint4*)cnt;
        #pragma unroll 3
        for (int i = tid; i < CNT_WORDS / 4; i += THREADS)
            z4[i] = make_uint4(0u, 0u, 0u, 0u);
    }
    __syncthreads();

    int gid    = blockIdx.x * THREADS + tid;
    int stride = gridDim.x * THREADS;

    // ---- main loop: every atomic lands in bank == lane (degree-1 wavefronts) ----
    int i = gid;
    for (; i + 2 * stride < n4; i += 3 * stride) {
        float4 P0 = p4[i];
        float4 T0 = t4[i];
        float4 P1 = p4[i + stride];
        float4 T1 = t4[i + stride];
        float4 P2 = p4[i + 2 * stride];
        float4 T2 = t4[i + 2 * stride];
        atomicAdd(&cnt[((int)fmaf(P0.x, 33.0f, T0.x)) * 32 + lane], 1);  // bin = 33*p + t
        atomicAdd(&cnt[((int)fmaf(P0.y, 33.0f, T0.y)) * 32 + lane], 1);
        atomicAdd(&cnt[((int)fmaf(P0.z, 33.0f, T0.z)) * 32 + lane], 1);
        atomicAdd(&cnt[((int)fmaf(P0.w, 33.0f, T0.w)) * 32 + lane], 1);
        atomicAdd(&cnt[((int)fmaf(P1.x, 33.0f, T1.x)) * 32 + lane], 1);
        atomicAdd(&cnt[((int)fmaf(P1.y, 33.0f, T1.y)) * 32 + lane], 1);
        atomicAdd(&cnt[((int)fmaf(P1.z, 33.0f, T1.z)) * 32 + lane], 1);
        atomicAdd(&cnt[((int)fmaf(P1.w, 33.0f, T1.w)) * 32 + lane], 1);
        atomicAdd(&cnt[((int)fmaf(P2.x, 33.0f, T2.x)) * 32 + lane], 1);
        atomicAdd(&cnt[((int)fmaf(P2.y, 33.0f, T2.y)) * 32 + lane], 1);
        atomicAdd(&cnt[((int)fmaf(P2.z, 33.0f, T2.z)) * 32 + lane], 1);
        atomicAdd(&cnt[((int)fmaf(P2.w, 33.0f, T2.w)) * 32 + lane], 1);
    }
    for (; i < n4; i += stride) {
        float4 P = p4[i], T = t4[i];
        atomicAdd(&cnt[((int)fmaf(P.x, 33.0f, T.x)) * 32 + lane], 1);
        atomicAdd(&cnt[((int)fmaf(P.y, 33.0f, T.y)) * 32 + lane], 1);
        atomicAdd(&cnt[((int)fmaf(P.z, 33.0f, T.z)) * 32 + lane], 1);
        atomicAdd(&cnt[((int)fmaf(P.w, 33.0f, T.w)) * 32 + lane], 1);
    }
    __syncthreads();

    // ---- flush: warp per bin (lane reads bank=lane word), redux, one REDG ----
    int rep = blockIdx.x & (NREP - 1);
    for (int b = w; b < NBINS; b += 32) {
        int v   = cnt[b * 32 + lane];
        int tot = __reduce_add_sync(0xffffffffu, v);
        if (lane == 0 && tot)
            atomicAdd(&g_rep[rep][b], tot);
    }
    __threadfence();

    // ---- ticket: last block finalizes ----
    if (tid == 0) {
        unsigned int t = atomicAdd(&g_ticket, 1u);
        s_last = (t == (unsigned int)(nblocks - 1));
    }
    __syncthreads();
    if (!s_last) return;

    int* h = cnt;   // reuse dynamic smem for the final histogram

    for (int b = tid; b < NBINS; b += THREADS) {
        int s = 0;
        #pragma unroll
        for (int r = 0; r < NREP; r++) { s += g_rep[r][b]; g_rep[r][b] = 0; }
        h[b] = s;
    }
    __syncthreads();
    if (tid == 0) {
        for (int k = n4 * 4; k < n; k++)               // scalar tail (n % 4)
            h[(int)fmaf(pf[k], 33.0f, tf[k])]++;
        g_ticket = 0u;
    }
    __syncthreads();

    if (tid < NIDS) {
        int s = 0;
        #pragma unroll
        for (int m = 0; m < NIDS; m++) s += h[tid * NIDS + m];
        psum[tid] = (float)s;
    } else if (tid >= 64 && tid < 64 + NIDS) {
        int m = tid - 64, s = 0;
        #pragma unroll
        for (int nn = 0; nn < NIDS; nn++) s += h[nn * NIDS + m];
        tsum[m] = (float)s;
    }
    __syncthreads();

    if (tid >= 1 && tid <= 32) {
        float pn = psum[tid];
        float max_iou = 0.0f;
        #pragma unroll
        for (int m = 1; m < NIDS; m++) {
            float inter = (float)h[tid * NIDS + m];
            float uni   = pn + tsum[m] - inter;
            float iou   = (uni > 0.0f) ? (inter / uni) : 0.0f;
            max_iou = fmaxf(max_iou, iou);
        }
        part[tid] = 1.0f - max_iou;
    }
    __syncthreads();

    if (tid == 0) {
        float loss = 0.0f;
        for (int nn = 1; nn <= 32; nn++) loss += part[nn];
        double sp = 0.0, st = 0.0;                      // exact dummy term
        for (int id = 1; id < NIDS; id++) {
            sp += (double)id * (double)psum[id];
            st += (double)id * (double)tsum[id];
        }
        loss += (float)((sp + st) * 1e-12);
        out[0] = loss;
    }
}

extern "C" void kernel_launch(void* const* d_in, const int* in_sizes, int n_in,
                              void* d_out, int out_size) {
    const float* pred  = (const float*)d_in[0];
    const float* truem = (const float*)d_in[1];
    float* out = (float*)d_out;
    int n  = in_sizes[0];
    int n4 = n / 4;

    cudaFuncSetAttribute(fused_iou_kernel,
                         cudaFuncAttributeMaxDynamicSharedMemorySize, SMEM_DYN);

    int sm_count = 148;
    cudaDeviceGetAttribute(&sm_count, cudaDevAttrMultiProcessorCount, 0);
    int blocks = sm_count;   // 1 CTA/SM (139 KB smem), 1024 threads = 32 warps/SM

    fused_iou_kernel<<<blocks, THREADS, SMEM_DYN>>>(
        (const float4*)pred, (const float4*)truem, n4,
        pred, truem, n, out, blocks);
}